// round 7
// baseline (speedup 1.0000x reference)
#include <cuda_runtime.h>
#include <math.h>
#include <stdint.h>

#define NN   200000
#define EE   600000
#define HH   128
#define OUTD 256
#define BMAXG 1024
#define BM   128
#define SCAN_B 512

#define ASTRIDE 68     // 64-col chunk + 4 pad
#define WSTRIDE 136    // 128-col + 8 pad

// ---------------- scratch (device globals; no allocation) ----------------
__device__ float g_bufA[(size_t)NN * HH];
__device__ float g_bufB[(size_t)NN * HH];
__device__ float g_agg [(size_t)NN * HH];
__device__ int   g_deg [NN];
__device__ int   g_cur [NN];
__device__ int   g_rowptr[NN + 1];
__device__ int   g_scanTmp[NN];
__device__ int   g_bsum[2048];
__device__ int   g_adj [2 * EE];
__device__ float g_invn[NN];
__device__ float g_gsum[BMAXG * HH];
__device__ int   g_cnt [BMAXG];

// ---------------- helpers ----------------
__device__ __forceinline__ void redAdd4(float* p, float4 v) {
    asm volatile("red.global.add.v4.f32 [%0], {%1,%2,%3,%4};"
                 :: "l"(p), "f"(v.x), "f"(v.y), "f"(v.z), "f"(v.w) : "memory");
}
__device__ __forceinline__ float gelu_exact(float v) {
    return 0.5f * v * (1.0f + erff(v * 0.70710678118654752f));
}
__device__ __forceinline__ float4 f4add(float4 a, float4 b) {
    return make_float4(a.x + b.x, a.y + b.y, a.z + b.z, a.w + b.w);
}
__device__ __forceinline__ float tf32r(float x) {
    float y;
    asm("cvt.rna.tf32.f32 %0, %1;" : "=f"(y) : "f"(x));
    return y;
}
__device__ __forceinline__ void mma_tf32(float* c, const uint32_t* a, uint32_t b0, uint32_t b1) {
    asm volatile(
        "mma.sync.aligned.m16n8k8.row.col.f32.tf32.tf32.f32 "
        "{%0,%1,%2,%3}, {%4,%5,%6,%7}, {%8,%9}, {%0,%1,%2,%3};"
        : "+f"(c[0]), "+f"(c[1]), "+f"(c[2]), "+f"(c[3])
        : "r"(a[0]), "r"(a[1]), "r"(a[2]), "r"(a[3]), "r"(b0), "r"(b1));
}

// ---------------- fused init ----------------
__global__ void init_k(int* __restrict__ deg, int* __restrict__ cur,
                       int* __restrict__ cnt, float* __restrict__ gsum,
                       int n, int b) {
    int i = blockIdx.x * blockDim.x + threadIdx.x;
    int s = gridDim.x * blockDim.x;
    for (int f = i; f < n; f += s) { deg[f] = 0; cur[f] = 0; }
    int g = b * HH;
    for (int f = i; f < g; f += s) gsum[f] = 0.f;
    for (int f = i; f < b; f += s) cnt[f] = 0;
}

// ---------------- degree ----------------
__global__ void deg_k(const int* __restrict__ src, const int* __restrict__ dst,
                      int* __restrict__ deg, int E) {
    int e = blockIdx.x * blockDim.x + threadIdx.x;
    if (e < E) {
        atomicAdd(&deg[src[e]], 1);
        atomicAdd(&deg[dst[e]], 1);
    }
}

// ---------------- exclusive scan (3-kernel) ----------------
__global__ void scan1_k(const int* __restrict__ deg, int* __restrict__ tmp,
                        int* __restrict__ bsum, int n) {
    __shared__ int s[SCAN_B];
    int i = blockIdx.x * SCAN_B + threadIdx.x;
    int v = (i < n) ? deg[i] : 0;
    s[threadIdx.x] = v;
    __syncthreads();
    for (int o = 1; o < SCAN_B; o <<= 1) {
        int t = 0;
        if ((int)threadIdx.x >= o) t = s[threadIdx.x - o];
        __syncthreads();
        if ((int)threadIdx.x >= o) s[threadIdx.x] += t;
        __syncthreads();
    }
    if (i < n) tmp[i] = s[threadIdx.x];
    if (threadIdx.x == SCAN_B - 1) bsum[blockIdx.x] = s[SCAN_B - 1];
}
__global__ void scan2_k(int* __restrict__ bsum, int nb) {
    __shared__ int s[1024];
    int v = ((int)threadIdx.x < nb) ? bsum[threadIdx.x] : 0;
    s[threadIdx.x] = v;
    __syncthreads();
    for (int o = 1; o < 1024; o <<= 1) {
        int t = 0;
        if ((int)threadIdx.x >= o) t = s[threadIdx.x - o];
        __syncthreads();
        if ((int)threadIdx.x >= o) s[threadIdx.x] += t;
        __syncthreads();
    }
    if ((int)threadIdx.x < nb) bsum[threadIdx.x] = s[threadIdx.x];
}
__global__ void scan3_k(const int* __restrict__ deg, const int* __restrict__ tmp,
                        const int* __restrict__ bsum, const int* __restrict__ batch,
                        int* __restrict__ rowptr, float* __restrict__ invn,
                        int* __restrict__ cnt, int n, int Edir) {
    int i = blockIdx.x * SCAN_B + threadIdx.x;
    if (i < n) {
        int boff = (blockIdx.x > 0) ? bsum[blockIdx.x - 1] : 0;
        int d = deg[i];
        rowptr[i] = tmp[i] - d + boff;
        invn[i] = rsqrtf(fmaxf((float)d, 1.0f));
        atomicAdd(&cnt[batch[i]], 1);
    }
    if (i == 0) rowptr[n] = Edir;
}

// ---------------- CSR fill ----------------
__global__ void fill_k(const int* __restrict__ src, const int* __restrict__ dst,
                       const int* __restrict__ rowptr, int* __restrict__ cur,
                       int* __restrict__ adj, int E) {
    int e = blockIdx.x * blockDim.x + threadIdx.x;
    if (e < E) {
        int s = src[e], d = dst[e];
        int p = atomicAdd(&cur[d], 1);
        adj[rowptr[d] + p] = s;
        int q = atomicAdd(&cur[s], 1);
        adj[rowptr[s] + q] = d;
    }
}

// ---------------- embedding gather ----------------
__global__ void gather_k(const int* __restrict__ x, const float* __restrict__ emb,
                         float* __restrict__ h, int n) {
    int gt = blockIdx.x * blockDim.x + threadIdx.x;
    int nd = gt >> 5, k4 = gt & 31;
    if (nd >= n) return;
    int t = x[nd];
    ((float4*)(h + (size_t)nd * HH))[k4] = ((const float4*)(emb + (size_t)t * HH))[k4];
}

// ---------------- layer-1 aggregation: sum emb[x[u]] from the hot 153KB table ----------------
__global__ void aggregate1_k(const int* __restrict__ x, const float* __restrict__ emb,
                             const int* __restrict__ rowptr, const int* __restrict__ adj,
                             const float* __restrict__ invn, float* __restrict__ agg, int n) {
    int lane = threadIdx.x & 31;
    int v = (blockIdx.x * blockDim.x + threadIdx.x) >> 5;
    if (v >= n) return;
    int beg = rowptr[v], end = rowptr[v + 1];
    float4 a0 = make_float4(0.f, 0.f, 0.f, 0.f);
    float4 a1 = a0, a2 = a0, a3 = a0;
    int i = beg;
    for (; i + 4 <= end; i += 4) {
        int t0 = __ldg(x + __ldg(adj + i));
        int t1 = __ldg(x + __ldg(adj + i + 1));
        int t2 = __ldg(x + __ldg(adj + i + 2));
        int t3 = __ldg(x + __ldg(adj + i + 3));
        a0 = f4add(a0, __ldg(((const float4*)(emb + (size_t)t0 * HH)) + lane));
        a1 = f4add(a1, __ldg(((const float4*)(emb + (size_t)t1 * HH)) + lane));
        a2 = f4add(a2, __ldg(((const float4*)(emb + (size_t)t2 * HH)) + lane));
        a3 = f4add(a3, __ldg(((const float4*)(emb + (size_t)t3 * HH)) + lane));
    }
    for (; i < end; i++) {
        int t = __ldg(x + __ldg(adj + i));
        a0 = f4add(a0, __ldg(((const float4*)(emb + (size_t)t * HH)) + lane));
    }
    float4 s = f4add(f4add(a0, a1), f4add(a2, a3));
    float sc = invn[v];
    s.x *= sc; s.y *= sc; s.z *= sc; s.w *= sc;
    ((float4*)(agg + (size_t)v * HH))[lane] = s;
}

// ---------------- layer-2 aggregation: random row gathers, 8-wide unroll ----------------
__global__ void aggregate_k(const float* __restrict__ h, const int* __restrict__ rowptr,
                            const int* __restrict__ adj, const float* __restrict__ invn,
                            float* __restrict__ agg, int n) {
    int lane = threadIdx.x & 31;
    int v = (blockIdx.x * blockDim.x + threadIdx.x) >> 5;
    if (v >= n) return;
    int beg = rowptr[v], end = rowptr[v + 1];
    float4 a0 = make_float4(0.f, 0.f, 0.f, 0.f);
    float4 a1 = a0, a2 = a0, a3 = a0;
    float4 a4 = a0, a5 = a0, a6 = a0, a7 = a0;
    int i = beg;
    for (; i + 8 <= end; i += 8) {
        int u0 = __ldg(adj + i);
        int u1 = __ldg(adj + i + 1);
        int u2 = __ldg(adj + i + 2);
        int u3 = __ldg(adj + i + 3);
        int u4 = __ldg(adj + i + 4);
        int u5 = __ldg(adj + i + 5);
        int u6 = __ldg(adj + i + 6);
        int u7 = __ldg(adj + i + 7);
        a0 = f4add(a0, __ldg(((const float4*)(h + (size_t)u0 * HH)) + lane));
        a1 = f4add(a1, __ldg(((const float4*)(h + (size_t)u1 * HH)) + lane));
        a2 = f4add(a2, __ldg(((const float4*)(h + (size_t)u2 * HH)) + lane));
        a3 = f4add(a3, __ldg(((const float4*)(h + (size_t)u3 * HH)) + lane));
        a4 = f4add(a4, __ldg(((const float4*)(h + (size_t)u4 * HH)) + lane));
        a5 = f4add(a5, __ldg(((const float4*)(h + (size_t)u5 * HH)) + lane));
        a6 = f4add(a6, __ldg(((const float4*)(h + (size_t)u6 * HH)) + lane));
        a7 = f4add(a7, __ldg(((const float4*)(h + (size_t)u7 * HH)) + lane));
    }
    if (i + 4 <= end) {
        int u0 = __ldg(adj + i);
        int u1 = __ldg(adj + i + 1);
        int u2 = __ldg(adj + i + 2);
        int u3 = __ldg(adj + i + 3);
        a0 = f4add(a0, __ldg(((const float4*)(h + (size_t)u0 * HH)) + lane));
        a1 = f4add(a1, __ldg(((const float4*)(h + (size_t)u1 * HH)) + lane));
        a2 = f4add(a2, __ldg(((const float4*)(h + (size_t)u2 * HH)) + lane));
        a3 = f4add(a3, __ldg(((const float4*)(h + (size_t)u3 * HH)) + lane));
        i += 4;
    }
    for (; i < end; i++) {
        int u = __ldg(adj + i);
        a0 = f4add(a0, __ldg(((const float4*)(h + (size_t)u * HH)) + lane));
    }
    float4 s = f4add(f4add(f4add(a0, a1), f4add(a2, a3)),
                     f4add(f4add(a4, a5), f4add(a6, a7)));
    float sc = invn[v];
    s.x *= sc; s.y *= sc; s.z *= sc; s.w *= sc;
    ((float4*)(agg + (size_t)v * HH))[lane] = s;
}

// ---------------- combine (TF32 tensor core): hout = gelu(agg@W + b + hprev) ----------------
__global__ void combine_tc_k(const float* __restrict__ agg, const float* __restrict__ hprev,
                             const float* __restrict__ W, const float* __restrict__ bias,
                             float* __restrict__ hout, int n) {
    extern __shared__ float smem[];
    float* As = smem;
    float* Ws = smem + 128 * ASTRIDE;
    int tid  = threadIdx.x;
    int lane = tid & 31;
    int warp = tid >> 5;
    int gid  = lane >> 2;
    int tig  = lane & 3;
    int wm   = warp >> 1;
    int wn   = warp & 1;
    int m0   = blockIdx.x * BM;
    int wm0  = wm * 32;
    int wn0  = wn * 64;

    float acc[2][8][4];
#pragma unroll
    for (int t = 0; t < 2; t++)
#pragma unroll
        for (int j = 0; j < 8; j++)
#pragma unroll
            for (int c = 0; c < 4; c++) acc[t][j][c] = 0.f;

#pragma unroll
    for (int kb = 0; kb < HH; kb += 64) {
        for (int f = tid; f < 128 * 16; f += 256) {
            int m = f >> 4, c4 = f & 15;
            int gm = m0 + m;
            float4 v = make_float4(0.f, 0.f, 0.f, 0.f);
            if (gm < n) v = __ldg((const float4*)(agg + (size_t)gm * HH + kb) + c4);
            v.x = tf32r(v.x); v.y = tf32r(v.y); v.z = tf32r(v.z); v.w = tf32r(v.w);
            *(float4*)(As + m * ASTRIDE + c4 * 4) = v;
        }
        for (int f = tid; f < 64 * 32; f += 256) {
            int k = f >> 5, n4 = f & 31;
            float4 v = __ldg((const float4*)(W + (size_t)(kb + k) * HH) + n4);
            v.x = tf32r(v.x); v.y = tf32r(v.y); v.z = tf32r(v.z); v.w = tf32r(v.w);
            *(float4*)(Ws + k * WSTRIDE + n4 * 4) = v;
        }
        __syncthreads();

#pragma unroll
        for (int kk = 0; kk < 64; kk += 8) {
            uint32_t afrag[2][4];
#pragma unroll
            for (int t = 0; t < 2; t++) {
                const float* ab = As + (wm0 + 16 * t + gid) * ASTRIDE + kk + tig;
                afrag[t][0] = __float_as_uint(ab[0]);
                afrag[t][1] = __float_as_uint(ab[8 * ASTRIDE]);
                afrag[t][2] = __float_as_uint(ab[4]);
                afrag[t][3] = __float_as_uint(ab[8 * ASTRIDE + 4]);
            }
#pragma unroll
            for (int j = 0; j < 8; j++) {
                const float* bb = Ws + (kk + tig) * WSTRIDE + wn0 + 8 * j + gid;
                uint32_t b0 = __float_as_uint(bb[0]);
                uint32_t b1 = __float_as_uint(bb[4 * WSTRIDE]);
                mma_tf32(acc[0][j], afrag[0], b0, b1);
                mma_tf32(acc[1][j], afrag[1], b0, b1);
            }
        }
        __syncthreads();
    }

#pragma unroll
    for (int j = 0; j < 8; j++) {
        int col = wn0 + 8 * j + 2 * tig;
        float2 bv = *(const float2*)(bias + col);
#pragma unroll
        for (int t = 0; t < 2; t++) {
            int r0 = m0 + wm0 + 16 * t + gid;
            if (r0 < n) {
                float2 hr = __ldg((const float2*)(hprev + (size_t)r0 * HH + col));
                float2 o;
                o.x = gelu_exact(acc[t][j][0] + bv.x + hr.x);
                o.y = gelu_exact(acc[t][j][1] + bv.y + hr.y);
                *(float2*)(hout + (size_t)r0 * HH + col) = o;
            }
            int r1 = r0 + 8;
            if (r1 < n) {
                float2 hr = __ldg((const float2*)(hprev + (size_t)r1 * HH + col));
                float2 o;
                o.x = gelu_exact(acc[t][j][2] + bv.x + hr.x);
                o.y = gelu_exact(acc[t][j][3] + bv.y + hr.y);
                *(float2*)(hout + (size_t)r1 * HH + col) = o;
            }
        }
    }
}

// ---------------- pooling ----------------
__global__ void pool_k(const float* __restrict__ h, const int* __restrict__ batch,
                       float* __restrict__ gsum, int n) {
    int gt = blockIdx.x * blockDim.x + threadIdx.x;
    int nd = gt >> 5, lane = gt & 31;
    if (nd >= n) return;
    int b = batch[nd];
    float4 v = ((const float4*)(h + (size_t)nd * HH))[lane];
    redAdd4(gsum + (size_t)b * HH + lane * 4, v);
}

// ---------------- final head ----------------
__global__ void final_k(const float* __restrict__ gsum, const int* __restrict__ cnt,
                        const float* __restrict__ Wo, const float* __restrict__ bo,
                        const float* __restrict__ gamma, const float* __restrict__ beta,
                        float* __restrict__ out) {
    __shared__ float g[HH];
    __shared__ float rs[8], rq[8];
    int b = blockIdx.x, tid = threadIdx.x;
    if (tid < HH) g[tid] = gsum[(size_t)b * HH + tid] / fmaxf((float)cnt[b], 1.0f);
    __syncthreads();
    float acc = bo[tid];
#pragma unroll 4
    for (int k = 0; k < HH; k++) acc = fmaf(g[k], Wo[k * OUTD + tid], acc);
    float s = acc, q = acc * acc;
#pragma unroll
    for (int o = 16; o; o >>= 1) {
        s += __shfl_xor_sync(0xFFFFFFFFu, s, o);
        q += __shfl_xor_sync(0xFFFFFFFFu, q, o);
    }
    int w = tid >> 5;
    if ((tid & 31) == 0) { rs[w] = s; rq[w] = q; }
    __syncthreads();
    float ts = 0.f, tq = 0.f;
#pragma unroll
    for (int i = 0; i < 8; i++) { ts += rs[i]; tq += rq[i]; }
    float mu  = ts * (1.0f / OUTD);
    float var = tq * (1.0f / OUTD) - mu * mu;
    out[(size_t)b * OUTD + tid] = (acc - mu) * rsqrtf(var + 1e-5f) * gamma[tid] + beta[tid];
}

// ---------------- launch ----------------
extern "C" void kernel_launch(void* const* d_in, const int* in_sizes, int n_in,
                              void* d_out, int out_size) {
    const int* x     = (const int*)d_in[0];
    const int* ei    = (const int*)d_in[1];
    const int* batch = (const int*)d_in[2];
    int off = (n_in >= 13 && in_sizes[3] == 1) ? 4 : 3;
    const float* emb   = (const float*)d_in[off + 0];
    const float* W0    = (const float*)d_in[off + 1];
    const float* b0    = (const float*)d_in[off + 2];
    const float* W1    = (const float*)d_in[off + 3];
    const float* b1    = (const float*)d_in[off + 4];
    const float* Wo    = (const float*)d_in[off + 5];
    const float* bo    = (const float*)d_in[off + 6];
    const float* gamma = (const float*)d_in[off + 7];
    const float* beta  = (const float*)d_in[off + 8];

    int N = in_sizes[0];
    int E = in_sizes[1] / 2;
    int B = out_size / OUTD;

    float *bufA, *bufB, *agg, *invn, *gsum;
    int *deg, *cur, *rowptr, *scanTmp, *bsum, *adj, *cnt;
    cudaGetSymbolAddress((void**)&bufA, g_bufA);
    cudaGetSymbolAddress((void**)&bufB, g_bufB);
    cudaGetSymbolAddress((void**)&agg,  g_agg);
    cudaGetSymbolAddress((void**)&invn, g_invn);
    cudaGetSymbolAddress((void**)&gsum, g_gsum);
    cudaGetSymbolAddress((void**)&deg,  g_deg);
    cudaGetSymbolAddress((void**)&cur,  g_cur);
    cudaGetSymbolAddress((void**)&rowptr, g_rowptr);
    cudaGetSymbolAddress((void**)&scanTmp, g_scanTmp);
    cudaGetSymbolAddress((void**)&bsum, g_bsum);
    cudaGetSymbolAddress((void**)&adj,  g_adj);
    cudaGetSymbolAddress((void**)&cnt,  g_cnt);

    int smem_tc = (128 * ASTRIDE + 64 * WSTRIDE) * 4;   // 69632 bytes
    cudaFuncSetAttribute(combine_tc_k, cudaFuncAttributeMaxDynamicSharedMemorySize, smem_tc);

    const int* src = ei;
    const int* dst = ei + E;

    int gthr = N * 32;
    int gblk = (gthr + 255) / 256;
    int cblk = (N + BM - 1) / BM;
    int nscan = (N + SCAN_B - 1) / SCAN_B;

    // init + CSR build
    init_k<<<256, 256>>>(deg, cur, cnt, gsum, N, B);
    deg_k<<<(E + 255) / 256, 256>>>(src, dst, deg, E);
    scan1_k<<<nscan, SCAN_B>>>(deg, scanTmp, bsum, N);
    scan2_k<<<1, 1024>>>(bsum, nscan);
    scan3_k<<<nscan, SCAN_B>>>(deg, scanTmp, bsum, batch, rowptr, invn, cnt, N, 2 * E);
    fill_k<<<(E + 255) / 256, 256>>>(src, dst, rowptr, cur, adj, E);

    // embedding
    gather_k<<<gblk, 256>>>(x, emb, bufA, N);

    // layer 1 (aggregate straight from the hot emb table)
    aggregate1_k<<<(N * 32 + 255) / 256, 256>>>(x, emb, rowptr, adj, invn, agg, N);
    combine_tc_k<<<cblk, 256, smem_tc>>>(agg, bufA, W0, b0, bufB, N);

    // layer 2
    aggregate_k<<<(N * 32 + 255) / 256, 256>>>(bufB, rowptr, adj, invn, agg, N);
    combine_tc_k<<<cblk, 256, smem_tc>>>(agg, bufB, W1, b1, bufA, N);

    // pool + head
    pool_k<<<gblk, 256>>>(bufA, batch, gsum, N);
    final_k<<<B, 256>>>(gsum, cnt, Wo, bo, gamma, beta, (float*)d_out);
}

// round 8
// speedup vs baseline: 1.5128x; 1.5128x over previous
#include <cuda_runtime.h>
#include <math.h>
#include <stdint.h>

#define NN   200000
#define EE   600000
#define HH   128
#define OUTD 256
#define BMAXG 1024
#define BM   128
#define SCAN_B 512

// tf32 GEMM tile params
#define ASTRIDE 68     // 64-col chunk + 4 pad
#define WSTRIDE 136    // 128-col + 8 pad

// ---------------- scratch (device globals; no allocation) ----------------
__device__ float g_bufA[(size_t)NN * HH];
__device__ float g_bufB[(size_t)NN * HH];
__device__ float g_agg [(size_t)NN * HH];
__device__ int   g_deg [NN];
__device__ int   g_cur [NN];
__device__ int   g_rowptr[NN + 1];
__device__ int   g_scanTmp[NN];
__device__ int   g_bsum[2048];
__device__ int   g_adj [2 * EE];
__device__ int   g_adjT[2 * EE];           // neighbor TYPE (x[u]) for layer-1 emb gather
__device__ float g_invn[NN];
__device__ float g_gsum[BMAXG * HH];
__device__ int   g_cnt [BMAXG];

// ---------------- helpers ----------------
__device__ __forceinline__ void redAdd4(float* p, float4 v) {
    asm volatile("red.global.add.v4.f32 [%0], {%1,%2,%3,%4};"
                 :: "l"(p), "f"(v.x), "f"(v.y), "f"(v.z), "f"(v.w) : "memory");
}
__device__ __forceinline__ float gelu_exact(float v) {
    return 0.5f * v * (1.0f + erff(v * 0.70710678118654752f));
}
__device__ __forceinline__ float4 f4add(float4 a, float4 b) {
    return make_float4(a.x + b.x, a.y + b.y, a.z + b.z, a.w + b.w);
}
__device__ __forceinline__ float tf32r(float x) {
    float y;
    asm("cvt.rna.tf32.f32 %0, %1;" : "=f"(y) : "f"(x));
    return y;
}
__device__ __forceinline__ void mma_tf32(float* c, const uint32_t* a, uint32_t b0, uint32_t b1) {
    asm volatile(
        "mma.sync.aligned.m16n8k8.row.col.f32.tf32.tf32.f32 "
        "{%0,%1,%2,%3}, {%4,%5,%6,%7}, {%8,%9}, {%0,%1,%2,%3};"
        : "+f"(c[0]), "+f"(c[1]), "+f"(c[2]), "+f"(c[3])
        : "r"(a[0]), "r"(a[1]), "r"(a[2]), "r"(a[3]), "r"(b0), "r"(b1));
}

// ---------------- zero kernels ----------------
__global__ void zero_f_k(float* p, int n4) {
    int i = blockIdx.x * blockDim.x + threadIdx.x;
    int s = gridDim.x * blockDim.x;
    float4 z = make_float4(0.f, 0.f, 0.f, 0.f);
    for (int f = i; f < n4; f += s) ((float4*)p)[f] = z;
}
__global__ void zero_i_k(int* p, int n) {
    int i = blockIdx.x * blockDim.x + threadIdx.x;
    int s = gridDim.x * blockDim.x;
    for (int f = i; f < n; f += s) p[f] = 0;
}

// ---------------- degree ----------------
__global__ void deg_k(const int* __restrict__ src, const int* __restrict__ dst,
                      int* __restrict__ deg, int E) {
    int e = blockIdx.x * blockDim.x + threadIdx.x;
    if (e < E) {
        atomicAdd(&deg[src[e]], 1);
        atomicAdd(&deg[dst[e]], 1);
    }
}

// ---------------- exclusive scan (3-kernel) ----------------
__global__ void scan1_k(const int* __restrict__ deg, int* __restrict__ tmp,
                        int* __restrict__ bsum, int n) {
    __shared__ int s[SCAN_B];
    int i = blockIdx.x * SCAN_B + threadIdx.x;
    int v = (i < n) ? deg[i] : 0;
    s[threadIdx.x] = v;
    __syncthreads();
    for (int o = 1; o < SCAN_B; o <<= 1) {
        int t = 0;
        if ((int)threadIdx.x >= o) t = s[threadIdx.x - o];
        __syncthreads();
        if ((int)threadIdx.x >= o) s[threadIdx.x] += t;
        __syncthreads();
    }
    if (i < n) tmp[i] = s[threadIdx.x];
    if (threadIdx.x == SCAN_B - 1) bsum[blockIdx.x] = s[SCAN_B - 1];
}
__global__ void scan2_k(int* __restrict__ bsum, int nb) {
    __shared__ int s[1024];
    int v = ((int)threadIdx.x < nb) ? bsum[threadIdx.x] : 0;
    s[threadIdx.x] = v;
    __syncthreads();
    for (int o = 1; o < 1024; o <<= 1) {
        int t = 0;
        if ((int)threadIdx.x >= o) t = s[threadIdx.x - o];
        __syncthreads();
        if ((int)threadIdx.x >= o) s[threadIdx.x] += t;
        __syncthreads();
    }
    if ((int)threadIdx.x < nb) bsum[threadIdx.x] = s[threadIdx.x];
}
__global__ void scan3_k(const int* __restrict__ deg, const int* __restrict__ tmp,
                        const int* __restrict__ bsum, int* __restrict__ rowptr,
                        int n, int Edir) {
    int i = blockIdx.x * SCAN_B + threadIdx.x;
    if (i < n) {
        int boff = (blockIdx.x > 0) ? bsum[blockIdx.x - 1] : 0;
        rowptr[i] = tmp[i] - deg[i] + boff;
    }
    if (i == 0) rowptr[n] = Edir;
}

// ---------------- CSR fill (also stores neighbor type into adjT) ----------------
__global__ void fill_k(const int* __restrict__ src, const int* __restrict__ dst,
                       const int* __restrict__ x, const int* __restrict__ rowptr,
                       int* __restrict__ cur, int* __restrict__ adj,
                       int* __restrict__ adjT, int E) {
    int e = blockIdx.x * blockDim.x + threadIdx.x;
    if (e < E) {
        int s = src[e], d = dst[e];
        int xs = __ldg(x + s), xd = __ldg(x + d);
        int p = atomicAdd(&cur[d], 1);
        int pd = rowptr[d] + p;
        adj[pd]  = s;
        adjT[pd] = xs;
        int q = atomicAdd(&cur[s], 1);
        int ps = rowptr[s] + q;
        adj[ps]  = d;
        adjT[ps] = xd;
    }
}

// ---------------- embedding gather + invnorm ----------------
__global__ void gather_k(const int* __restrict__ x, const float* __restrict__ emb,
                         const int* __restrict__ deg, float* __restrict__ h,
                         float* __restrict__ invn, int n) {
    int gt = blockIdx.x * blockDim.x + threadIdx.x;
    int nd = gt >> 5, k4 = gt & 31;
    if (nd >= n) return;
    int t = x[nd];
    ((float4*)(h + (size_t)nd * HH))[k4] = ((const float4*)(emb + (size_t)t * HH))[k4];
    if (k4 == 0) invn[nd] = rsqrtf(fmaxf((float)deg[nd], 1.0f));
}

// ---------------- layer-1 aggregation: adjT -> hot 153KB emb table ----------------
__global__ void aggregate1_k(const float* __restrict__ emb, const int* __restrict__ rowptr,
                             const int* __restrict__ adjT, const float* __restrict__ invn,
                             float* __restrict__ agg, int n) {
    int lane = threadIdx.x & 31;
    int v = (blockIdx.x * blockDim.x + threadIdx.x) >> 5;
    if (v >= n) return;
    int beg = rowptr[v], end = rowptr[v + 1];
    float4 a0 = make_float4(0.f, 0.f, 0.f, 0.f);
    float4 a1 = a0, a2 = a0, a3 = a0;
    int i = beg;
    for (; i + 4 <= end; i += 4) {
        int t0 = __ldg(adjT + i);
        int t1 = __ldg(adjT + i + 1);
        int t2 = __ldg(adjT + i + 2);
        int t3 = __ldg(adjT + i + 3);
        a0 = f4add(a0, __ldg(((const float4*)(emb + (size_t)t0 * HH)) + lane));
        a1 = f4add(a1, __ldg(((const float4*)(emb + (size_t)t1 * HH)) + lane));
        a2 = f4add(a2, __ldg(((const float4*)(emb + (size_t)t2 * HH)) + lane));
        a3 = f4add(a3, __ldg(((const float4*)(emb + (size_t)t3 * HH)) + lane));
    }
    for (; i < end; i++) {
        int t = __ldg(adjT + i);
        a0 = f4add(a0, __ldg(((const float4*)(emb + (size_t)t * HH)) + lane));
    }
    float4 s = f4add(f4add(a0, a1), f4add(a2, a3));
    float sc = invn[v];
    s.x *= sc; s.y *= sc; s.z *= sc; s.w *= sc;
    ((float4*)(agg + (size_t)v * HH))[lane] = s;
}

// ---------------- layer-2 aggregation (R4-proven, 4-wide) ----------------
__global__ void aggregate_k(const float* __restrict__ h, const int* __restrict__ rowptr,
                            const int* __restrict__ adj, const float* __restrict__ invn,
                            float* __restrict__ agg, int n) {
    int lane = threadIdx.x & 31;
    int v = (blockIdx.x * blockDim.x + threadIdx.x) >> 5;
    if (v >= n) return;
    int beg = rowptr[v], end = rowptr[v + 1];
    float4 a0 = make_float4(0.f, 0.f, 0.f, 0.f);
    float4 a1 = a0, a2 = a0, a3 = a0;
    int i = beg;
    for (; i + 4 <= end; i += 4) {
        int u0 = __ldg(adj + i);
        int u1 = __ldg(adj + i + 1);
        int u2 = __ldg(adj + i + 2);
        int u3 = __ldg(adj + i + 3);
        a0 = f4add(a0, __ldg(((const float4*)(h + (size_t)u0 * HH)) + lane));
        a1 = f4add(a1, __ldg(((const float4*)(h + (size_t)u1 * HH)) + lane));
        a2 = f4add(a2, __ldg(((const float4*)(h + (size_t)u2 * HH)) + lane));
        a3 = f4add(a3, __ldg(((const float4*)(h + (size_t)u3 * HH)) + lane));
    }
    for (; i < end; i++) {
        int u = __ldg(adj + i);
        a0 = f4add(a0, __ldg(((const float4*)(h + (size_t)u * HH)) + lane));
    }
    float4 s = f4add(f4add(a0, a1), f4add(a2, a3));
    float sc = invn[v];
    s.x *= sc; s.y *= sc; s.z *= sc; s.w *= sc;
    ((float4*)(agg + (size_t)v * HH))[lane] = s;
}

// ---------------- combine (TF32 tensor core): hout = gelu(agg@W + b + hprev) ----------------
__global__ void combine_tc_k(const float* __restrict__ agg, const float* __restrict__ hprev,
                             const float* __restrict__ W, const float* __restrict__ bias,
                             float* __restrict__ hout, int n) {
    extern __shared__ float smem[];
    float* As = smem;
    float* Ws = smem + 128 * ASTRIDE;
    int tid  = threadIdx.x;
    int lane = tid & 31;
    int warp = tid >> 5;
    int gid  = lane >> 2;
    int tig  = lane & 3;
    int wm   = warp >> 1;
    int wn   = warp & 1;
    int m0   = blockIdx.x * BM;
    int wm0  = wm * 32;
    int wn0  = wn * 64;

    float acc[2][8][4];
#pragma unroll
    for (int t = 0; t < 2; t++)
#pragma unroll
        for (int j = 0; j < 8; j++)
#pragma unroll
            for (int c = 0; c < 4; c++) acc[t][j][c] = 0.f;

#pragma unroll
    for (int kb = 0; kb < HH; kb += 64) {
        for (int f = tid; f < 128 * 16; f += 256) {
            int m = f >> 4, c4 = f & 15;
            int gm = m0 + m;
            float4 v = make_float4(0.f, 0.f, 0.f, 0.f);
            if (gm < n) v = __ldg((const float4*)(agg + (size_t)gm * HH + kb) + c4);
            v.x = tf32r(v.x); v.y = tf32r(v.y); v.z = tf32r(v.z); v.w = tf32r(v.w);
            *(float4*)(As + m * ASTRIDE + c4 * 4) = v;
        }
        for (int f = tid; f < 64 * 32; f += 256) {
            int k = f >> 5, n4 = f & 31;
            float4 v = __ldg((const float4*)(W + (size_t)(kb + k) * HH) + n4);
            v.x = tf32r(v.x); v.y = tf32r(v.y); v.z = tf32r(v.z); v.w = tf32r(v.w);
            *(float4*)(Ws + k * WSTRIDE + n4 * 4) = v;
        }
        __syncthreads();

#pragma unroll
        for (int kk = 0; kk < 64; kk += 8) {
            uint32_t afrag[2][4];
#pragma unroll
            for (int t = 0; t < 2; t++) {
                const float* ab = As + (wm0 + 16 * t + gid) * ASTRIDE + kk + tig;
                afrag[t][0] = __float_as_uint(ab[0]);
                afrag[t][1] = __float_as_uint(ab[8 * ASTRIDE]);
                afrag[t][2] = __float_as_uint(ab[4]);
                afrag[t][3] = __float_as_uint(ab[8 * ASTRIDE + 4]);
            }
#pragma unroll
            for (int j = 0; j < 8; j++) {
                const float* bb = Ws + (kk + tig) * WSTRIDE + wn0 + 8 * j + gid;
                uint32_t b0 = __float_as_uint(bb[0]);
                uint32_t b1 = __float_as_uint(bb[4 * WSTRIDE]);
                mma_tf32(acc[0][j], afrag[0], b0, b1);
                mma_tf32(acc[1][j], afrag[1], b0, b1);
            }
        }
        __syncthreads();
    }

#pragma unroll
    for (int j = 0; j < 8; j++) {
        int col = wn0 + 8 * j + 2 * tig;
        float2 bv = *(const float2*)(bias + col);
#pragma unroll
        for (int t = 0; t < 2; t++) {
            int r0 = m0 + wm0 + 16 * t + gid;
            if (r0 < n) {
                float2 hr = __ldg((const float2*)(hprev + (size_t)r0 * HH + col));
                float2 o;
                o.x = gelu_exact(acc[t][j][0] + bv.x + hr.x);
                o.y = gelu_exact(acc[t][j][1] + bv.y + hr.y);
                *(float2*)(hout + (size_t)r0 * HH + col) = o;
            }
            int r1 = r0 + 8;
            if (r1 < n) {
                float2 hr = __ldg((const float2*)(hprev + (size_t)r1 * HH + col));
                float2 o;
                o.x = gelu_exact(acc[t][j][2] + bv.x + hr.x);
                o.y = gelu_exact(acc[t][j][3] + bv.y + hr.y);
                *(float2*)(hout + (size_t)r1 * HH + col) = o;
            }
        }
    }
}

// ---------------- pooling ----------------
__global__ void pool_k(const float* __restrict__ h, const int* __restrict__ batch,
                       float* __restrict__ gsum, int* __restrict__ cnt, int n) {
    int gt = blockIdx.x * blockDim.x + threadIdx.x;
    int nd = gt >> 5, lane = gt & 31;
    if (nd >= n) return;
    int b = batch[nd];
    float4 v = ((const float4*)(h + (size_t)nd * HH))[lane];
    redAdd4(gsum + (size_t)b * HH + lane * 4, v);
    if (lane == 0) atomicAdd(&cnt[b], 1);
}

// ---------------- final head ----------------
__global__ void final_k(const float* __restrict__ gsum, const int* __restrict__ cnt,
                        const float* __restrict__ Wo, const float* __restrict__ bo,
                        const float* __restrict__ gamma, const float* __restrict__ beta,
                        float* __restrict__ out) {
    __shared__ float g[HH];
    __shared__ float rs[8], rq[8];
    int b = blockIdx.x, tid = threadIdx.x;
    if (tid < HH) g[tid] = gsum[(size_t)b * HH + tid] / fmaxf((float)cnt[b], 1.0f);
    __syncthreads();
    float acc = bo[tid];
#pragma unroll 4
    for (int k = 0; k < HH; k++) acc = fmaf(g[k], Wo[k * OUTD + tid], acc);
    float s = acc, q = acc * acc;
#pragma unroll
    for (int o = 16; o; o >>= 1) {
        s += __shfl_xor_sync(0xFFFFFFFFu, s, o);
        q += __shfl_xor_sync(0xFFFFFFFFu, q, o);
    }
    int w = tid >> 5;
    if ((tid & 31) == 0) { rs[w] = s; rq[w] = q; }
    __syncthreads();
    float ts = 0.f, tq = 0.f;
#pragma unroll
    for (int i = 0; i < 8; i++) { ts += rs[i]; tq += rq[i]; }
    float mu  = ts * (1.0f / OUTD);
    float var = tq * (1.0f / OUTD) - mu * mu;
    out[(size_t)b * OUTD + tid] = (acc - mu) * rsqrtf(var + 1e-5f) * gamma[tid] + beta[tid];
}

// ---------------- launch ----------------
extern "C" void kernel_launch(void* const* d_in, const int* in_sizes, int n_in,
                              void* d_out, int out_size) {
    const int* x     = (const int*)d_in[0];
    const int* ei    = (const int*)d_in[1];
    const int* batch = (const int*)d_in[2];
    int off = (n_in >= 13 && in_sizes[3] == 1) ? 4 : 3;
    const float* emb   = (const float*)d_in[off + 0];
    const float* W0    = (const float*)d_in[off + 1];
    const float* b0    = (const float*)d_in[off + 2];
    const float* W1    = (const float*)d_in[off + 3];
    const float* b1    = (const float*)d_in[off + 4];
    const float* Wo    = (const float*)d_in[off + 5];
    const float* bo    = (const float*)d_in[off + 6];
    const float* gamma = (const float*)d_in[off + 7];
    const float* beta  = (const float*)d_in[off + 8];

    int N = in_sizes[0];
    int E = in_sizes[1] / 2;
    int B = out_size / OUTD;

    float *bufA, *bufB, *agg, *invn, *gsum;
    int *deg, *cur, *rowptr, *scanTmp, *bsum, *adj, *adjT, *cnt;
    cudaGetSymbolAddress((void**)&bufA, g_bufA);
    cudaGetSymbolAddress((void**)&bufB, g_bufB);
    cudaGetSymbolAddress((void**)&agg,  g_agg);
    cudaGetSymbolAddress((void**)&invn, g_invn);
    cudaGetSymbolAddress((void**)&gsum, g_gsum);
    cudaGetSymbolAddress((void**)&deg,  g_deg);
    cudaGetSymbolAddress((void**)&cur,  g_cur);
    cudaGetSymbolAddress((void**)&rowptr, g_rowptr);
    cudaGetSymbolAddress((void**)&scanTmp, g_scanTmp);
    cudaGetSymbolAddress((void**)&bsum, g_bsum);
    cudaGetSymbolAddress((void**)&adj,  g_adj);
    cudaGetSymbolAddress((void**)&adjT, g_adjT);
    cudaGetSymbolAddress((void**)&cnt,  g_cnt);

    int smem_tc = (128 * ASTRIDE + 64 * WSTRIDE) * 4;   // 69632 bytes
    cudaFuncSetAttribute(combine_tc_k, cudaFuncAttributeMaxDynamicSharedMemorySize, smem_tc);

    const int* src = ei;
    const int* dst = ei + E;

    int gthr = N * 32;
    int gblk = (gthr + 255) / 256;
    int cblk = (N + BM - 1) / BM;
    int nscan = (N + SCAN_B - 1) / SCAN_B;

    // degree + CSR build
    zero_i_k<<<256, 256>>>(deg, N);
    deg_k<<<(E + 255) / 256, 256>>>(src, dst, deg, E);
    scan1_k<<<nscan, SCAN_B>>>(deg, scanTmp, bsum, N);
    scan2_k<<<1, 1024>>>(bsum, nscan);
    scan3_k<<<nscan, SCAN_B>>>(deg, scanTmp, bsum, rowptr, N, 2 * E);
    zero_i_k<<<256, 256>>>(cur, N);
    fill_k<<<(E + 255) / 256, 256>>>(src, dst, x, rowptr, cur, adj, adjT, E);

    // embedding + invnorm
    gather_k<<<gblk, 256>>>(x, emb, deg, bufA, invn, N);

    // layer 1 (aggregate from hot emb table via precomputed neighbor types)
    aggregate1_k<<<(N * 32 + 255) / 256, 256>>>(emb, rowptr, adjT, invn, agg, N);
    combine_tc_k<<<cblk, 256, smem_tc>>>(agg, bufA, W0, b0, bufB, N);

    // layer 2
    aggregate_k<<<(N * 32 + 255) / 256, 256>>>(bufB, rowptr, adj, invn, agg, N);
    combine_tc_k<<<cblk, 256, smem_tc>>>(agg, bufB, W1, b1, bufA, N);

    // pooling + head
    zero_f_k<<<64, 256>>>(gsum, B * HH / 4);
    zero_i_k<<<1, 256>>>(cnt, B);
    pool_k<<<gblk, 256>>>(bufA, batch, gsum, cnt, N);
    final_k<<<B, 256>>>(gsum, cnt, Wo, bo, gamma, beta, (float*)d_out);
}

// round 9
// speedup vs baseline: 1.6272x; 1.0757x over previous
#include <cuda_runtime.h>
#include <math.h>
#include <stdint.h>

#define NN   200000
#define EE   600000
#define HH   128
#define OUTD 256
#define BMAXG 1024
#define BM   128
#define SCAN_B 512

// tf32 GEMM tile params
#define ASTRIDE 68     // 64-col chunk + 4 pad
#define WSTRIDE 136    // 128-col + 8 pad

// ---------------- scratch (device globals; no allocation) ----------------
__device__ float g_bufA[(size_t)NN * HH];
__device__ float g_bufB[(size_t)NN * HH];
__device__ float g_agg [(size_t)NN * HH];
__device__ int   g_deg [NN];
__device__ int   g_cur [NN];
__device__ int   g_rowptr[NN + 1];
__device__ int   g_scanTmp[NN];
__device__ int   g_bsum[2048];
__device__ int   g_adj [2 * EE];
__device__ int   g_adjT[2 * EE];           // neighbor TYPE (x[u]) for layer-1 emb gather
__device__ float g_invn[NN];
__device__ float g_gsum[BMAXG * HH];
__device__ int   g_cnt [BMAXG];

// ---------------- helpers ----------------
__device__ __forceinline__ void redAdd4(float* p, float4 v) {
    asm volatile("red.global.add.v4.f32 [%0], {%1,%2,%3,%4};"
                 :: "l"(p), "f"(v.x), "f"(v.y), "f"(v.z), "f"(v.w) : "memory");
}
__device__ __forceinline__ float gelu_exact(float v) {
    return 0.5f * v * (1.0f + erff(v * 0.70710678118654752f));
}
__device__ __forceinline__ float4 f4add(float4 a, float4 b) {
    return make_float4(a.x + b.x, a.y + b.y, a.z + b.z, a.w + b.w);
}
__device__ __forceinline__ float tf32r(float x) {
    float y;
    asm("cvt.rna.tf32.f32 %0, %1;" : "=f"(y) : "f"(x));
    return y;
}
__device__ __forceinline__ void mma_tf32(float* c, const uint32_t* a, uint32_t b0, uint32_t b1) {
    asm volatile(
        "mma.sync.aligned.m16n8k8.row.col.f32.tf32.tf32.f32 "
        "{%0,%1,%2,%3}, {%4,%5,%6,%7}, {%8,%9}, {%0,%1,%2,%3};"
        : "+f"(c[0]), "+f"(c[1]), "+f"(c[2]), "+f"(c[3])
        : "r"(a[0]), "r"(a[1]), "r"(a[2]), "r"(a[3]), "r"(b0), "r"(b1));
}

// ---------------- fused init: zero deg, cur, cnt, gsum ----------------
__global__ void init_k(int* __restrict__ deg, int* __restrict__ cur,
                       int* __restrict__ cnt, float* __restrict__ gsum,
                       int n, int b) {
    int i = blockIdx.x * blockDim.x + threadIdx.x;
    int s = gridDim.x * blockDim.x;
    for (int f = i; f < n; f += s) { deg[f] = 0; cur[f] = 0; }
    int g = b * HH;
    for (int f = i; f < g; f += s) gsum[f] = 0.f;
    for (int f = i; f < b; f += s) cnt[f] = 0;
}

// ---------------- degree ----------------
__global__ void deg_k(const int* __restrict__ src, const int* __restrict__ dst,
                      int* __restrict__ deg, int E) {
    int e = blockIdx.x * blockDim.x + threadIdx.x;
    if (e < E) {
        atomicAdd(&deg[src[e]], 1);
        atomicAdd(&deg[dst[e]], 1);
    }
}

// ---------------- exclusive scan (3-kernel) ----------------
__global__ void scan1_k(const int* __restrict__ deg, int* __restrict__ tmp,
                        int* __restrict__ bsum, int n) {
    __shared__ int s[SCAN_B];
    int i = blockIdx.x * SCAN_B + threadIdx.x;
    int v = (i < n) ? deg[i] : 0;
    s[threadIdx.x] = v;
    __syncthreads();
    for (int o = 1; o < SCAN_B; o <<= 1) {
        int t = 0;
        if ((int)threadIdx.x >= o) t = s[threadIdx.x - o];
        __syncthreads();
        if ((int)threadIdx.x >= o) s[threadIdx.x] += t;
        __syncthreads();
    }
    if (i < n) tmp[i] = s[threadIdx.x];
    if (threadIdx.x == SCAN_B - 1) bsum[blockIdx.x] = s[SCAN_B - 1];
}
__global__ void scan2_k(int* __restrict__ bsum, int nb) {
    __shared__ int s[1024];
    int v = ((int)threadIdx.x < nb) ? bsum[threadIdx.x] : 0;
    s[threadIdx.x] = v;
    __syncthreads();
    for (int o = 1; o < 1024; o <<= 1) {
        int t = 0;
        if ((int)threadIdx.x >= o) t = s[threadIdx.x - o];
        __syncthreads();
        if ((int)threadIdx.x >= o) s[threadIdx.x] += t;
        __syncthreads();
    }
    if ((int)threadIdx.x < nb) bsum[threadIdx.x] = s[threadIdx.x];
}
// scan3: rowptr + invn + per-graph node counts
__global__ void scan3_k(const int* __restrict__ deg, const int* __restrict__ tmp,
                        const int* __restrict__ bsum, const int* __restrict__ batch,
                        int* __restrict__ rowptr, float* __restrict__ invn,
                        int* __restrict__ cnt, int n, int Edir) {
    int i = blockIdx.x * SCAN_B + threadIdx.x;
    if (i < n) {
        int boff = (blockIdx.x > 0) ? bsum[blockIdx.x - 1] : 0;
        int d = deg[i];
        rowptr[i] = tmp[i] - d + boff;
        invn[i] = rsqrtf(fmaxf((float)d, 1.0f));
        atomicAdd(&cnt[batch[i]], 1);
    }
    if (i == 0) rowptr[n] = Edir;
}

// ---------------- CSR fill (also stores neighbor type into adjT) ----------------
__global__ void fill_k(const int* __restrict__ src, const int* __restrict__ dst,
                       const int* __restrict__ x, const int* __restrict__ rowptr,
                       int* __restrict__ cur, int* __restrict__ adj,
                       int* __restrict__ adjT, int E) {
    int e = blockIdx.x * blockDim.x + threadIdx.x;
    if (e < E) {
        int s = src[e], d = dst[e];
        int xs = __ldg(x + s), xd = __ldg(x + d);
        int p = atomicAdd(&cur[d], 1);
        int pd = rowptr[d] + p;
        adj[pd]  = s;
        adjT[pd] = xs;
        int q = atomicAdd(&cur[s], 1);
        int ps = rowptr[s] + q;
        adj[ps]  = d;
        adjT[ps] = xd;
    }
}

// ---------------- layer-1 aggregation: adjT -> hot 153KB emb table ----------------
__global__ void aggregate1_k(const float* __restrict__ emb, const int* __restrict__ rowptr,
                             const int* __restrict__ adjT, const float* __restrict__ invn,
                             float* __restrict__ agg, int n) {
    int lane = threadIdx.x & 31;
    int v = (blockIdx.x * blockDim.x + threadIdx.x) >> 5;
    if (v >= n) return;
    int beg = rowptr[v], end = rowptr[v + 1];
    float4 a0 = make_float4(0.f, 0.f, 0.f, 0.f);
    float4 a1 = a0, a2 = a0, a3 = a0;
    int i = beg;
    for (; i + 4 <= end; i += 4) {
        int t0 = __ldg(adjT + i);
        int t1 = __ldg(adjT + i + 1);
        int t2 = __ldg(adjT + i + 2);
        int t3 = __ldg(adjT + i + 3);
        a0 = f4add(a0, __ldg(((const float4*)(emb + (size_t)t0 * HH)) + lane));
        a1 = f4add(a1, __ldg(((const float4*)(emb + (size_t)t1 * HH)) + lane));
        a2 = f4add(a2, __ldg(((const float4*)(emb + (size_t)t2 * HH)) + lane));
        a3 = f4add(a3, __ldg(((const float4*)(emb + (size_t)t3 * HH)) + lane));
    }
    for (; i < end; i++) {
        int t = __ldg(adjT + i);
        a0 = f4add(a0, __ldg(((const float4*)(emb + (size_t)t * HH)) + lane));
    }
    float4 s = f4add(f4add(a0, a1), f4add(a2, a3));
    float sc = invn[v];
    s.x *= sc; s.y *= sc; s.z *= sc; s.w *= sc;
    ((float4*)(agg + (size_t)v * HH))[lane] = s;
}

// ---------------- layer-2 aggregation: flat predicated 8-wide gather ----------------
__global__ void aggregate_k(const float* __restrict__ h, const int* __restrict__ rowptr,
                            const int* __restrict__ adj, const float* __restrict__ invn,
                            float* __restrict__ agg, int n) {
    int lane = threadIdx.x & 31;
    int v = (blockIdx.x * blockDim.x + threadIdx.x) >> 5;
    if (v >= n) return;
    int beg = rowptr[v], end = rowptr[v + 1];
    int d = end - beg;
    float4 a0 = make_float4(0.f, 0.f, 0.f, 0.f);
    float4 a1 = a0, a2 = a0, a3 = a0;
    if (d > 0) {
        // flat 8-wide: clamp index so all 8 loads are valid & independent (dups = L1 hits)
        int dm1 = d - 1;
        int u[8];
#pragma unroll
        for (int j = 0; j < 8; j++)
            u[j] = __ldg(adj + beg + (j < dm1 ? j : dm1));
        float4 vv[8];
#pragma unroll
        for (int j = 0; j < 8; j++)
            vv[j] = __ldg(((const float4*)(h + (size_t)u[j] * HH)) + lane);
#pragma unroll
        for (int j = 0; j < 8; j++) {
            if (j < d) {
                if ((j & 3) == 0) a0 = f4add(a0, vv[j]);
                else if ((j & 3) == 1) a1 = f4add(a1, vv[j]);
                else if ((j & 3) == 2) a2 = f4add(a2, vv[j]);
                else a3 = f4add(a3, vv[j]);
            }
        }
        // remainder for high-degree rows
        int i = beg + 8;
        for (; i + 4 <= end; i += 4) {
            int u0 = __ldg(adj + i);
            int u1 = __ldg(adj + i + 1);
            int u2 = __ldg(adj + i + 2);
            int u3 = __ldg(adj + i + 3);
            a0 = f4add(a0, __ldg(((const float4*)(h + (size_t)u0 * HH)) + lane));
            a1 = f4add(a1, __ldg(((const float4*)(h + (size_t)u1 * HH)) + lane));
            a2 = f4add(a2, __ldg(((const float4*)(h + (size_t)u2 * HH)) + lane));
            a3 = f4add(a3, __ldg(((const float4*)(h + (size_t)u3 * HH)) + lane));
        }
        for (; i < end; i++) {
            int uu = __ldg(adj + i);
            a0 = f4add(a0, __ldg(((const float4*)(h + (size_t)uu * HH)) + lane));
        }
    }
    float4 s = f4add(f4add(a0, a1), f4add(a2, a3));
    float sc = invn[v];
    s.x *= sc; s.y *= sc; s.z *= sc; s.w *= sc;
    ((float4*)(agg + (size_t)v * HH))[lane] = s;
}

// ---------------- combine (TF32 tensor core) ----------------
// RES_EMB=1: residual = emb[x[row]] (hot-table indirect). RES_EMB=0: residual = hprev[row].
template <int RES_EMB>
__global__ void combine_tc_k(const float* __restrict__ agg, const float* __restrict__ hprev,
                             const int* __restrict__ xres, const float* __restrict__ embres,
                             const float* __restrict__ W, const float* __restrict__ bias,
                             float* __restrict__ hout, int n) {
    extern __shared__ float smem[];
    float* As = smem;
    float* Ws = smem + 128 * ASTRIDE;
    int tid  = threadIdx.x;
    int lane = tid & 31;
    int warp = tid >> 5;
    int gid  = lane >> 2;
    int tig  = lane & 3;
    int wm   = warp >> 1;
    int wn   = warp & 1;
    int m0   = blockIdx.x * BM;
    int wm0  = wm * 32;
    int wn0  = wn * 64;

    float acc[2][8][4];
#pragma unroll
    for (int t = 0; t < 2; t++)
#pragma unroll
        for (int j = 0; j < 8; j++)
#pragma unroll
            for (int c = 0; c < 4; c++) acc[t][j][c] = 0.f;

#pragma unroll
    for (int kb = 0; kb < HH; kb += 64) {
        for (int f = tid; f < 128 * 16; f += 256) {
            int m = f >> 4, c4 = f & 15;
            int gm = m0 + m;
            float4 v = make_float4(0.f, 0.f, 0.f, 0.f);
            if (gm < n) v = __ldg((const float4*)(agg + (size_t)gm * HH + kb) + c4);
            v.x = tf32r(v.x); v.y = tf32r(v.y); v.z = tf32r(v.z); v.w = tf32r(v.w);
            *(float4*)(As + m * ASTRIDE + c4 * 4) = v;
        }
        for (int f = tid; f < 64 * 32; f += 256) {
            int k = f >> 5, n4 = f & 31;
            float4 v = __ldg((const float4*)(W + (size_t)(kb + k) * HH) + n4);
            v.x = tf32r(v.x); v.y = tf32r(v.y); v.z = tf32r(v.z); v.w = tf32r(v.w);
            *(float4*)(Ws + k * WSTRIDE + n4 * 4) = v;
        }
        __syncthreads();

#pragma unroll
        for (int kk = 0; kk < 64; kk += 8) {
            uint32_t afrag[2][4];
#pragma unroll
            for (int t = 0; t < 2; t++) {
                const float* ab = As + (wm0 + 16 * t + gid) * ASTRIDE + kk + tig;
                afrag[t][0] = __float_as_uint(ab[0]);
                afrag[t][1] = __float_as_uint(ab[8 * ASTRIDE]);
                afrag[t][2] = __float_as_uint(ab[4]);
                afrag[t][3] = __float_as_uint(ab[8 * ASTRIDE + 4]);
            }
#pragma unroll
            for (int j = 0; j < 8; j++) {
                const float* bb = Ws + (kk + tig) * WSTRIDE + wn0 + 8 * j + gid;
                uint32_t b0 = __float_as_uint(bb[0]);
                uint32_t b1 = __float_as_uint(bb[4 * WSTRIDE]);
                mma_tf32(acc[0][j], afrag[0], b0, b1);
                mma_tf32(acc[1][j], afrag[1], b0, b1);
            }
        }
        __syncthreads();
    }

    // epilogue: bias + residual + exact GELU
#pragma unroll
    for (int t = 0; t < 2; t++) {
#pragma unroll
        for (int half = 0; half < 2; half++) {
            int row = m0 + wm0 + 16 * t + gid + 8 * half;
            if (row >= n) continue;
            const float* hp;
            if (RES_EMB) {
                hp = embres + (size_t)__ldg(xres + row) * HH;
            } else {
                hp = hprev + (size_t)row * HH;
            }
            float* op = hout + (size_t)row * HH;
#pragma unroll
            for (int j = 0; j < 8; j++) {
                int col = wn0 + 8 * j + 2 * tig;
                float2 bv = *(const float2*)(bias + col);
                float2 hr = __ldg((const float2*)(hp + col));
                float2 o;
                o.x = gelu_exact(acc[t][j][2 * half]     + bv.x + hr.x);
                o.y = gelu_exact(acc[t][j][2 * half + 1] + bv.y + hr.y);
                *(float2*)(op + col) = o;
            }
        }
    }
}

// ---------------- pooling ----------------
__global__ void pool_k(const float* __restrict__ h, const int* __restrict__ batch,
                       float* __restrict__ gsum, int n) {
    int gt = blockIdx.x * blockDim.x + threadIdx.x;
    int nd = gt >> 5, lane = gt & 31;
    if (nd >= n) return;
    int b = batch[nd];
    float4 v = ((const float4*)(h + (size_t)nd * HH))[lane];
    redAdd4(gsum + (size_t)b * HH + lane * 4, v);
}

// ---------------- final head ----------------
__global__ void final_k(const float* __restrict__ gsum, const int* __restrict__ cnt,
                        const float* __restrict__ Wo, const float* __restrict__ bo,
                        const float* __restrict__ gamma, const float* __restrict__ beta,
                        float* __restrict__ out) {
    __shared__ float g[HH];
    __shared__ float rs[8], rq[8];
    int b = blockIdx.x, tid = threadIdx.x;
    if (tid < HH) g[tid] = gsum[(size_t)b * HH + tid] / fmaxf((float)cnt[b], 1.0f);
    __syncthreads();
    float acc = bo[tid];
#pragma unroll 4
    for (int k = 0; k < HH; k++) acc = fmaf(g[k], Wo[k * OUTD + tid], acc);
    float s = acc, q = acc * acc;
#pragma unroll
    for (int o = 16; o; o >>= 1) {
        s += __shfl_xor_sync(0xFFFFFFFFu, s, o);
        q += __shfl_xor_sync(0xFFFFFFFFu, q, o);
    }
    int w = tid >> 5;
    if ((tid & 31) == 0) { rs[w] = s; rq[w] = q; }
    __syncthreads();
    float ts = 0.f, tq = 0.f;
#pragma unroll
    for (int i = 0; i < 8; i++) { ts += rs[i]; tq += rq[i]; }
    float mu  = ts * (1.0f / OUTD);
    float var = tq * (1.0f / OUTD) - mu * mu;
    out[(size_t)b * OUTD + tid] = (acc - mu) * rsqrtf(var + 1e-5f) * gamma[tid] + beta[tid];
}

// ---------------- launch ----------------
extern "C" void kernel_launch(void* const* d_in, const int* in_sizes, int n_in,
                              void* d_out, int out_size) {
    const int* x     = (const int*)d_in[0];
    const int* ei    = (const int*)d_in[1];
    const int* batch = (const int*)d_in[2];
    int off = (n_in >= 13 && in_sizes[3] == 1) ? 4 : 3;
    const float* emb   = (const float*)d_in[off + 0];
    const float* W0    = (const float*)d_in[off + 1];
    const float* b0    = (const float*)d_in[off + 2];
    const float* W1    = (const float*)d_in[off + 3];
    const float* b1    = (const float*)d_in[off + 4];
    const float* Wo    = (const float*)d_in[off + 5];
    const float* bo    = (const float*)d_in[off + 6];
    const float* gamma = (const float*)d_in[off + 7];
    const float* beta  = (const float*)d_in[off + 8];

    int N = in_sizes[0];
    int E = in_sizes[1] / 2;
    int B = out_size / OUTD;

    float *bufA, *bufB, *agg, *invn, *gsum;
    int *deg, *cur, *rowptr, *scanTmp, *bsum, *adj, *adjT, *cnt;
    cudaGetSymbolAddress((void**)&bufA, g_bufA);
    cudaGetSymbolAddress((void**)&bufB, g_bufB);
    cudaGetSymbolAddress((void**)&agg,  g_agg);
    cudaGetSymbolAddress((void**)&invn, g_invn);
    cudaGetSymbolAddress((void**)&gsum, g_gsum);
    cudaGetSymbolAddress((void**)&deg,  g_deg);
    cudaGetSymbolAddress((void**)&cur,  g_cur);
    cudaGetSymbolAddress((void**)&rowptr, g_rowptr);
    cudaGetSymbolAddress((void**)&scanTmp, g_scanTmp);
    cudaGetSymbolAddress((void**)&bsum, g_bsum);
    cudaGetSymbolAddress((void**)&adj,  g_adj);
    cudaGetSymbolAddress((void**)&adjT, g_adjT);
    cudaGetSymbolAddress((void**)&cnt,  g_cnt);

    int smem_tc = (128 * ASTRIDE + 64 * WSTRIDE) * 4;   // 69632 bytes
    cudaFuncSetAttribute(combine_tc_k<0>, cudaFuncAttributeMaxDynamicSharedMemorySize, smem_tc);
    cudaFuncSetAttribute(combine_tc_k<1>, cudaFuncAttributeMaxDynamicSharedMemorySize, smem_tc);

    const int* src = ei;
    const int* dst = ei + E;

    int gthr = N * 32;
    int gblk = (gthr + 255) / 256;
    int cblk = (N + BM - 1) / BM;
    int nscan = (N + SCAN_B - 1) / SCAN_B;

    // init + CSR build
    init_k<<<256, 256>>>(deg, cur, cnt, gsum, N, B);
    deg_k<<<(E + 255) / 256, 256>>>(src, dst, deg, E);
    scan1_k<<<nscan, SCAN_B>>>(deg, scanTmp, bsum, N);
    scan2_k<<<1, 1024>>>(bsum, nscan);
    scan3_k<<<nscan, SCAN_B>>>(deg, scanTmp, bsum, batch, rowptr, invn, cnt, N, 2 * E);
    fill_k<<<(E + 255) / 256, 256>>>(src, dst, x, rowptr, cur, adj, adjT, E);

    // layer 1 (aggregate from hot emb table; residual read directly as emb[x[row]])
    aggregate1_k<<<(N * 32 + 255) / 256, 256>>>(emb, rowptr, adjT, invn, agg, N);
    combine_tc_k<1><<<cblk, 256, smem_tc>>>(agg, nullptr, x, emb, W0, b0, bufB, N);

    // layer 2
    aggregate_k<<<(N * 32 + 255) / 256, 256>>>(bufB, rowptr, adj, invn, agg, N);
    combine_tc_k<0><<<cblk, 256, smem_tc>>>(agg, bufB, nullptr, nullptr, W1, b1, bufA, N);

    // pool + head
    pool_k<<<gblk, 256>>>(bufA, batch, gsum, N);
    final_k<<<B, 256>>>(gsum, cnt, Wo, bo, gamma, beta, (float*)d_out);
}

// round 10
// speedup vs baseline: 1.6387x; 1.0070x over previous
#include <cuda_runtime.h>
#include <cuda_bf16.h>
#include <math.h>
#include <stdint.h>

#define NN   200000
#define EE   600000
#define HH   128
#define OUTD 256
#define BMAXG 1024
#define BM   128
#define SCAN_B 512

// tf32 GEMM tile params
#define ASTRIDE 68     // 64-col chunk + 4 pad
#define WSTRIDE 136    // 128-col + 8 pad

// ---------------- scratch (device globals; no allocation) ----------------
__device__ float g_bufA[(size_t)NN * HH];
__device__ float g_bufB[(size_t)NN * HH];
__device__ __nv_bfloat16 g_bufB16[(size_t)NN * HH];   // 51.2 MB — fits L2
__device__ float g_agg [(size_t)NN * HH];
__device__ int   g_deg [NN];
__device__ int   g_cur [NN];
__device__ int   g_rowptr[NN + 1];
__device__ int   g_scanTmp[NN];
__device__ int   g_bsum[2048];
__device__ int   g_adj [2 * EE];
__device__ int   g_adjT[2 * EE];
__device__ float g_invn[NN];
__device__ float g_gsum[BMAXG * HH];
__device__ int   g_cnt [BMAXG];

// ---------------- helpers ----------------
__device__ __forceinline__ void redAdd4(float* p, float4 v) {
    asm volatile("red.global.add.v4.f32 [%0], {%1,%2,%3,%4};"
                 :: "l"(p), "f"(v.x), "f"(v.y), "f"(v.z), "f"(v.w) : "memory");
}
__device__ __forceinline__ float gelu_exact(float v) {
    return 0.5f * v * (1.0f + erff(v * 0.70710678118654752f));
}
__device__ __forceinline__ float4 f4add(float4 a, float4 b) {
    return make_float4(a.x + b.x, a.y + b.y, a.z + b.z, a.w + b.w);
}
__device__ __forceinline__ float tf32r(float x) {
    float y;
    asm("cvt.rna.tf32.f32 %0, %1;" : "=f"(y) : "f"(x));
    return y;
}
__device__ __forceinline__ float4 bf4tof4(uint2 r) {
    float4 f;
    f.x = __uint_as_float(r.x << 16);
    f.y = __uint_as_float(r.x & 0xFFFF0000u);
    f.z = __uint_as_float(r.y << 16);
    f.w = __uint_as_float(r.y & 0xFFFF0000u);
    return f;
}
__device__ __forceinline__ void mma_tf32(float* c, const uint32_t* a, uint32_t b0, uint32_t b1) {
    asm volatile(
        "mma.sync.aligned.m16n8k8.row.col.f32.tf32.tf32.f32 "
        "{%0,%1,%2,%3}, {%4,%5,%6,%7}, {%8,%9}, {%0,%1,%2,%3};"
        : "+f"(c[0]), "+f"(c[1]), "+f"(c[2]), "+f"(c[3])
        : "r"(a[0]), "r"(a[1]), "r"(a[2]), "r"(a[3]), "r"(b0), "r"(b1));
}

// ---------------- fused init ----------------
__global__ void init_k(int* __restrict__ deg, int* __restrict__ cur,
                       int* __restrict__ cnt, float* __restrict__ gsum,
                       int n, int b) {
    int i = blockIdx.x * blockDim.x + threadIdx.x;
    int s = gridDim.x * blockDim.x;
    for (int f = i; f < n; f += s) { deg[f] = 0; cur[f] = 0; }
    int g = b * HH;
    for (int f = i; f < g; f += s) gsum[f] = 0.f;
    for (int f = i; f < b; f += s) cnt[f] = 0;
}

// ---------------- degree ----------------
__global__ void deg_k(const int* __restrict__ src, const int* __restrict__ dst,
                      int* __restrict__ deg, int E) {
    int e = blockIdx.x * blockDim.x + threadIdx.x;
    if (e < E) {
        atomicAdd(&deg[src[e]], 1);
        atomicAdd(&deg[dst[e]], 1);
    }
}

// ---------------- exclusive scan (3-kernel) ----------------
__global__ void scan1_k(const int* __restrict__ deg, int* __restrict__ tmp,
                        int* __restrict__ bsum, int n) {
    __shared__ int s[SCAN_B];
    int i = blockIdx.x * SCAN_B + threadIdx.x;
    int v = (i < n) ? deg[i] : 0;
    s[threadIdx.x] = v;
    __syncthreads();
    for (int o = 1; o < SCAN_B; o <<= 1) {
        int t = 0;
        if ((int)threadIdx.x >= o) t = s[threadIdx.x - o];
        __syncthreads();
        if ((int)threadIdx.x >= o) s[threadIdx.x] += t;
        __syncthreads();
    }
    if (i < n) tmp[i] = s[threadIdx.x];
    if (threadIdx.x == SCAN_B - 1) bsum[blockIdx.x] = s[SCAN_B - 1];
}
__global__ void scan2_k(int* __restrict__ bsum, int nb) {
    __shared__ int s[1024];
    int v = ((int)threadIdx.x < nb) ? bsum[threadIdx.x] : 0;
    s[threadIdx.x] = v;
    __syncthreads();
    for (int o = 1; o < 1024; o <<= 1) {
        int t = 0;
        if ((int)threadIdx.x >= o) t = s[threadIdx.x - o];
        __syncthreads();
        if ((int)threadIdx.x >= o) s[threadIdx.x] += t;
        __syncthreads();
    }
    if ((int)threadIdx.x < nb) bsum[threadIdx.x] = s[threadIdx.x];
}
__global__ void scan3_k(const int* __restrict__ deg, const int* __restrict__ tmp,
                        const int* __restrict__ bsum, const int* __restrict__ batch,
                        int* __restrict__ rowptr, float* __restrict__ invn,
                        int* __restrict__ cnt, int n, int Edir) {
    int i = blockIdx.x * SCAN_B + threadIdx.x;
    if (i < n) {
        int boff = (blockIdx.x > 0) ? bsum[blockIdx.x - 1] : 0;
        int d = deg[i];
        rowptr[i] = tmp[i] - d + boff;
        invn[i] = rsqrtf(fmaxf((float)d, 1.0f));
        atomicAdd(&cnt[batch[i]], 1);
    }
    if (i == 0) rowptr[n] = Edir;
}

// ---------------- CSR fill ----------------
__global__ void fill_k(const int* __restrict__ src, const int* __restrict__ dst,
                       const int* __restrict__ x, const int* __restrict__ rowptr,
                       int* __restrict__ cur, int* __restrict__ adj,
                       int* __restrict__ adjT, int E) {
    int e = blockIdx.x * blockDim.x + threadIdx.x;
    if (e < E) {
        int s = src[e], d = dst[e];
        int xs = __ldg(x + s), xd = __ldg(x + d);
        int p = atomicAdd(&cur[d], 1);
        int pd = rowptr[d] + p;
        adj[pd]  = s;
        adjT[pd] = xs;
        int q = atomicAdd(&cur[s], 1);
        int ps = rowptr[s] + q;
        adj[ps]  = d;
        adjT[ps] = xd;
    }
}

// ---------------- layer-1 aggregation: adjT -> hot 153KB emb table ----------------
__global__ void aggregate1_k(const float* __restrict__ emb, const int* __restrict__ rowptr,
                             const int* __restrict__ adjT, const float* __restrict__ invn,
                             float* __restrict__ agg, int n) {
    int lane = threadIdx.x & 31;
    int v = (blockIdx.x * blockDim.x + threadIdx.x) >> 5;
    if (v >= n) return;
    int beg = rowptr[v], end = rowptr[v + 1];
    float4 a0 = make_float4(0.f, 0.f, 0.f, 0.f);
    float4 a1 = a0, a2 = a0, a3 = a0;
    int i = beg;
    for (; i + 4 <= end; i += 4) {
        int t0 = __ldg(adjT + i);
        int t1 = __ldg(adjT + i + 1);
        int t2 = __ldg(adjT + i + 2);
        int t3 = __ldg(adjT + i + 3);
        a0 = f4add(a0, __ldg(((const float4*)(emb + (size_t)t0 * HH)) + lane));
        a1 = f4add(a1, __ldg(((const float4*)(emb + (size_t)t1 * HH)) + lane));
        a2 = f4add(a2, __ldg(((const float4*)(emb + (size_t)t2 * HH)) + lane));
        a3 = f4add(a3, __ldg(((const float4*)(emb + (size_t)t3 * HH)) + lane));
    }
    for (; i < end; i++) {
        int t = __ldg(adjT + i);
        a0 = f4add(a0, __ldg(((const float4*)(emb + (size_t)t * HH)) + lane));
    }
    float4 s = f4add(f4add(a0, a1), f4add(a2, a3));
    float sc = invn[v];
    s.x *= sc; s.y *= sc; s.z *= sc; s.w *= sc;
    ((float4*)(agg + (size_t)v * HH))[lane] = s;
}

// ---------------- layer-2 aggregation: flat 8-wide gather from L2-resident bf16 buffer ----------------
__global__ void aggregate_k(const __nv_bfloat16* __restrict__ h16, const int* __restrict__ rowptr,
                            const int* __restrict__ adj, const float* __restrict__ invn,
                            float* __restrict__ agg, int n) {
    int lane = threadIdx.x & 31;
    int v = (blockIdx.x * blockDim.x + threadIdx.x) >> 5;
    if (v >= n) return;
    int beg = rowptr[v], end = rowptr[v + 1];
    int d = end - beg;
    float4 a0 = make_float4(0.f, 0.f, 0.f, 0.f);
    float4 a1 = a0, a2 = a0, a3 = a0;
    if (d > 0) {
        int dm1 = d - 1;
        int u[8];
#pragma unroll
        for (int j = 0; j < 8; j++)
            u[j] = __ldg(adj + beg + (j < dm1 ? j : dm1));
        uint2 vv[8];
#pragma unroll
        for (int j = 0; j < 8; j++)
            vv[j] = __ldg(((const uint2*)(h16 + (size_t)u[j] * HH)) + lane);
#pragma unroll
        for (int j = 0; j < 8; j++) {
            if (j < d) {
                float4 f = bf4tof4(vv[j]);
                if ((j & 3) == 0) a0 = f4add(a0, f);
                else if ((j & 3) == 1) a1 = f4add(a1, f);
                else if ((j & 3) == 2) a2 = f4add(a2, f);
                else a3 = f4add(a3, f);
            }
        }
        int i = beg + 8;
        for (; i + 4 <= end; i += 4) {
            int u0 = __ldg(adj + i);
            int u1 = __ldg(adj + i + 1);
            int u2 = __ldg(adj + i + 2);
            int u3 = __ldg(adj + i + 3);
            a0 = f4add(a0, bf4tof4(__ldg(((const uint2*)(h16 + (size_t)u0 * HH)) + lane)));
            a1 = f4add(a1, bf4tof4(__ldg(((const uint2*)(h16 + (size_t)u1 * HH)) + lane)));
            a2 = f4add(a2, bf4tof4(__ldg(((const uint2*)(h16 + (size_t)u2 * HH)) + lane)));
            a3 = f4add(a3, bf4tof4(__ldg(((const uint2*)(h16 + (size_t)u3 * HH)) + lane)));
        }
        for (; i < end; i++) {
            int uu = __ldg(adj + i);
            a0 = f4add(a0, bf4tof4(__ldg(((const uint2*)(h16 + (size_t)uu * HH)) + lane)));
        }
    }
    float4 s = f4add(f4add(a0, a1), f4add(a2, a3));
    float sc = invn[v];
    s.x *= sc; s.y *= sc; s.z *= sc; s.w *= sc;
    // note: lane covers 4 floats -> agg float4 index = lane
    ((float4*)(agg + (size_t)v * HH))[lane] = s;
}

// ---------------- combine (TF32 tensor core) ----------------
// RES_EMB=1: residual = emb[x[row]].  STORE_BF16=1: also store bf16 shadow copy.
template <int RES_EMB, int STORE_BF16>
__global__ void combine_tc_k(const float* __restrict__ agg, const float* __restrict__ hprev,
                             const int* __restrict__ xres, const float* __restrict__ embres,
                             const float* __restrict__ W, const float* __restrict__ bias,
                             float* __restrict__ hout, __nv_bfloat16* __restrict__ hout16,
                             int n) {
    extern __shared__ float smem[];
    float* As = smem;
    float* Ws = smem + 128 * ASTRIDE;
    int tid  = threadIdx.x;
    int lane = tid & 31;
    int warp = tid >> 5;
    int gid  = lane >> 2;
    int tig  = lane & 3;
    int wm   = warp >> 1;
    int wn   = warp & 1;
    int m0   = blockIdx.x * BM;
    int wm0  = wm * 32;
    int wn0  = wn * 64;

    float acc[2][8][4];
#pragma unroll
    for (int t = 0; t < 2; t++)
#pragma unroll
        for (int j = 0; j < 8; j++)
#pragma unroll
            for (int c = 0; c < 4; c++) acc[t][j][c] = 0.f;

#pragma unroll
    for (int kb = 0; kb < HH; kb += 64) {
        for (int f = tid; f < 128 * 16; f += 256) {
            int m = f >> 4, c4 = f & 15;
            int gm = m0 + m;
            float4 v = make_float4(0.f, 0.f, 0.f, 0.f);
            if (gm < n) v = __ldg((const float4*)(agg + (size_t)gm * HH + kb) + c4);
            v.x = tf32r(v.x); v.y = tf32r(v.y); v.z = tf32r(v.z); v.w = tf32r(v.w);
            *(float4*)(As + m * ASTRIDE + c4 * 4) = v;
        }
        for (int f = tid; f < 64 * 32; f += 256) {
            int k = f >> 5, n4 = f & 31;
            float4 v = __ldg((const float4*)(W + (size_t)(kb + k) * HH) + n4);
            v.x = tf32r(v.x); v.y = tf32r(v.y); v.z = tf32r(v.z); v.w = tf32r(v.w);
            *(float4*)(Ws + k * WSTRIDE + n4 * 4) = v;
        }
        __syncthreads();

#pragma unroll
        for (int kk = 0; kk < 64; kk += 8) {
            uint32_t afrag[2][4];
#pragma unroll
            for (int t = 0; t < 2; t++) {
                const float* ab = As + (wm0 + 16 * t + gid) * ASTRIDE + kk + tig;
                afrag[t][0] = __float_as_uint(ab[0]);
                afrag[t][1] = __float_as_uint(ab[8 * ASTRIDE]);
                afrag[t][2] = __float_as_uint(ab[4]);
                afrag[t][3] = __float_as_uint(ab[8 * ASTRIDE + 4]);
            }
#pragma unroll
            for (int j = 0; j < 8; j++) {
                const float* bb = Ws + (kk + tig) * WSTRIDE + wn0 + 8 * j + gid;
                uint32_t b0 = __float_as_uint(bb[0]);
                uint32_t b1 = __float_as_uint(bb[4 * WSTRIDE]);
                mma_tf32(acc[0][j], afrag[0], b0, b1);
                mma_tf32(acc[1][j], afrag[1], b0, b1);
            }
        }
        __syncthreads();
    }

    // epilogue: bias + residual + exact GELU (+ optional bf16 shadow store)
#pragma unroll
    for (int t = 0; t < 2; t++) {
#pragma unroll
        for (int half = 0; half < 2; half++) {
            int row = m0 + wm0 + 16 * t + gid + 8 * half;
            if (row >= n) continue;
            const float* hp;
            if (RES_EMB) {
                hp = embres + (size_t)__ldg(xres + row) * HH;
            } else {
                hp = hprev + (size_t)row * HH;
            }
            float* op = hout + (size_t)row * HH;
#pragma unroll
            for (int j = 0; j < 8; j++) {
                int col = wn0 + 8 * j + 2 * tig;
                float2 bv = *(const float2*)(bias + col);
                float2 hr = __ldg((const float2*)(hp + col));
                float2 o;
                o.x = gelu_exact(acc[t][j][2 * half]     + bv.x + hr.x);
                o.y = gelu_exact(acc[t][j][2 * half + 1] + bv.y + hr.y);
                *(float2*)(op + col) = o;
                if (STORE_BF16) {
                    __nv_bfloat162 hb = __float22bfloat162_rn(o);
                    *(__nv_bfloat162*)(hout16 + (size_t)row * HH + col) = hb;
                }
            }
        }
    }
}

// ---------------- pooling ----------------
__global__ void pool_k(const float* __restrict__ h, const int* __restrict__ batch,
                       float* __restrict__ gsum, int n) {
    int gt = blockIdx.x * blockDim.x + threadIdx.x;
    int nd = gt >> 5, lane = gt & 31;
    if (nd >= n) return;
    int b = batch[nd];
    float4 v = ((const float4*)(h + (size_t)nd * HH))[lane];
    redAdd4(gsum + (size_t)b * HH + lane * 4, v);
}

// ---------------- final head ----------------
__global__ void final_k(const float* __restrict__ gsum, const int* __restrict__ cnt,
                        const float* __restrict__ Wo, const float* __restrict__ bo,
                        const float* __restrict__ gamma, const float* __restrict__ beta,
                        float* __restrict__ out) {
    __shared__ float g[HH];
    __shared__ float rs[8], rq[8];
    int b = blockIdx.x, tid = threadIdx.x;
    if (tid < HH) g[tid] = gsum[(size_t)b * HH + tid] / fmaxf((float)cnt[b], 1.0f);
    __syncthreads();
    float acc = bo[tid];
#pragma unroll 4
    for (int k = 0; k < HH; k++) acc = fmaf(g[k], Wo[k * OUTD + tid], acc);
    float s = acc, q = acc * acc;
#pragma unroll
    for (int o = 16; o; o >>= 1) {
        s += __shfl_xor_sync(0xFFFFFFFFu, s, o);
        q += __shfl_xor_sync(0xFFFFFFFFu, q, o);
    }
    int w = tid >> 5;
    if ((tid & 31) == 0) { rs[w] = s; rq[w] = q; }
    __syncthreads();
    float ts = 0.f, tq = 0.f;
#pragma unroll
    for (int i = 0; i < 8; i++) { ts += rs[i]; tq += rq[i]; }
    float mu  = ts * (1.0f / OUTD);
    float var = tq * (1.0f / OUTD) - mu * mu;
    out[(size_t)b * OUTD + tid] = (acc - mu) * rsqrtf(var + 1e-5f) * gamma[tid] + beta[tid];
}

// ---------------- launch ----------------
extern "C" void kernel_launch(void* const* d_in, const int* in_sizes, int n_in,
                              void* d_out, int out_size) {
    const int* x     = (const int*)d_in[0];
    const int* ei    = (const int*)d_in[1];
    const int* batch = (const int*)d_in[2];
    int off = (n_in >= 13 && in_sizes[3] == 1) ? 4 : 3;
    const float* emb   = (const float*)d_in[off + 0];
    const float* W0    = (const float*)d_in[off + 1];
    const float* b0    = (const float*)d_in[off + 2];
    const float* W1    = (const float*)d_in[off + 3];
    const float* b1    = (const float*)d_in[off + 4];
    const float* Wo    = (const float*)d_in[off + 5];
    const float* bo    = (const float*)d_in[off + 6];
    const float* gamma = (const float*)d_in[off + 7];
    const float* beta  = (const float*)d_in[off + 8];

    int N = in_sizes[0];
    int E = in_sizes[1] / 2;
    int B = out_size / OUTD;

    float *bufA, *bufB, *agg, *invn, *gsum;
    __nv_bfloat16* bufB16;
    int *deg, *cur, *rowptr, *scanTmp, *bsum, *adj, *adjT, *cnt;
    cudaGetSymbolAddress((void**)&bufA, g_bufA);
    cudaGetSymbolAddress((void**)&bufB, g_bufB);
    cudaGetSymbolAddress((void**)&bufB16, g_bufB16);
    cudaGetSymbolAddress((void**)&agg,  g_agg);
    cudaGetSymbolAddress((void**)&invn, g_invn);
    cudaGetSymbolAddress((void**)&gsum, g_gsum);
    cudaGetSymbolAddress((void**)&deg,  g_deg);
    cudaGetSymbolAddress((void**)&cur,  g_cur);
    cudaGetSymbolAddress((void**)&rowptr, g_rowptr);
    cudaGetSymbolAddress((void**)&scanTmp, g_scanTmp);
    cudaGetSymbolAddress((void**)&bsum, g_bsum);
    cudaGetSymbolAddress((void**)&adj,  g_adj);
    cudaGetSymbolAddress((void**)&adjT, g_adjT);
    cudaGetSymbolAddress((void**)&cnt,  g_cnt);

    int smem_tc = (128 * ASTRIDE + 64 * WSTRIDE) * 4;   // 69632 bytes
    cudaFuncSetAttribute((const void*)combine_tc_k<1,1>, cudaFuncAttributeMaxDynamicSharedMemorySize, smem_tc);
    cudaFuncSetAttribute((const void*)combine_tc_k<0,0>, cudaFuncAttributeMaxDynamicSharedMemorySize, smem_tc);

    const int* src = ei;
    const int* dst = ei + E;

    int gthr = N * 32;
    int gblk = (gthr + 255) / 256;
    int cblk = (N + BM - 1) / BM;
    int nscan = (N + SCAN_B - 1) / SCAN_B;

    // init + CSR build
    init_k<<<256, 256>>>(deg, cur, cnt, gsum, N, B);
    deg_k<<<(E + 255) / 256, 256>>>(src, dst, deg, E);
    scan1_k<<<nscan, SCAN_B>>>(deg, scanTmp, bsum, N);
    scan2_k<<<1, 1024>>>(bsum, nscan);
    scan3_k<<<nscan, SCAN_B>>>(deg, scanTmp, bsum, batch, rowptr, invn, cnt, N, 2 * E);
    fill_k<<<(E + 255) / 256, 256>>>(src, dst, x, rowptr, cur, adj, adjT, E);

    // layer 1: aggregate from hot emb table; combine writes fp32 + bf16 shadow
    aggregate1_k<<<(N * 32 + 255) / 256, 256>>>(emb, rowptr, adjT, invn, agg, N);
    combine_tc_k<1,1><<<cblk, 256, smem_tc>>>(agg, nullptr, x, emb, W0, b0, bufB, bufB16, N);

    // layer 2: gather from L2-resident bf16 shadow
    aggregate_k<<<(N * 32 + 255) / 256, 256>>>(bufB16, rowptr, adj, invn, agg, N);
    combine_tc_k<0,0><<<cblk, 256, smem_tc>>>(agg, bufB, nullptr, nullptr, W1, b1, bufA, nullptr, N);

    // pool + head
    pool_k<<<gblk, 256>>>(bufA, batch, gsum, N);
    final_k<<<B, 256>>>(gsum, cnt, Wo, bo, gamma, beta, (float*)d_out);
}